// round 4
// baseline (speedup 1.0000x reference)
#include <cuda_runtime.h>
#include <cuda_fp16.h>
#include <math.h>

#define N_NODES 16384
#define N_EDGES 32768
#define NG 256
#define TPG 12
#define NT (NG*TPG)
#define D 64

__device__ float  g_out[N_NODES*D];
__device__ float  g_h  [N_NODES*D];
__device__ float  g_he [N_EDGES*D];
__device__ __half g_ew [(size_t)N_EDGES*D*D];
__device__ float  g_agg[N_NODES*D];
__device__ float  g_m  [N_NODES*D];
__device__ float  g_gi [N_NODES*3*D];
__device__ float  g_gh [N_NODES*3*D];
__device__ float  g_deg[N_NODES];
__device__ float  g_wih_t[D*3*D];
__device__ float  g_whh_t[D*3*D];
__device__ float  g_s2s_wih_t[2*D*4*D];
__device__ float  g_s2s_whh_t[D*4*D];
__device__ float  g_mem_wih_t[2*D*4*D];
__device__ float  g_lin1_t[5*D*D];
__device__ float  g_e2t[D*64*D];
__device__ float  g_hx[NG*D];

__device__ __forceinline__ float sigf(float x) { return 1.0f/(1.0f+expf(-x)); }

__global__ void k_prep(const float* __restrict__ gru_wih, const float* __restrict__ gru_whh,
                       const float* __restrict__ s2s_wih, const float* __restrict__ s2s_whh,
                       const float* __restrict__ mem_wih, const float* __restrict__ lin1_w,
                       const float* __restrict__ e2_w)
{
    int i = blockIdx.x*blockDim.x + threadIdx.x;
    if (i < 64*4096) { int k = i/4096, j = i%4096; g_e2t[i] = e2_w[j*64+k]; }
    if (i < 64*192)  { int k = i/192,  j = i%192;  g_wih_t[i] = gru_wih[j*64+k];
                                                   g_whh_t[i] = gru_whh[j*64+k]; }
    if (i < 128*256) { int k = i/256,  j = i%256;  g_s2s_wih_t[i] = s2s_wih[j*128+k];
                                                   g_mem_wih_t[i] = mem_wih[j*128+k]; }
    if (i < 64*256)  { int k = i/256,  j = i%256;  g_s2s_whh_t[i] = s2s_whh[j*64+k]; }
    if (i < 320*64)  { int q = i/64,   j = i%64;   g_lin1_t[i] = lin1_w[j*320+q]; }
}

__global__ void k_node_init(const float* __restrict__ x, const float* __restrict__ w,
                            const float* __restrict__ b)
{
    int i = blockIdx.x*blockDim.x + threadIdx.x;
    int n = i >> 6, j = i & 63;
    float acc = b[j];
    #pragma unroll
    for (int k = 0; k < 3; k++) acc += x[n*3+k]*w[j*3+k];
    float v = fmaxf(acc, 0.f);
    g_out[i] = v; g_h[i] = v;
}

__global__ void k_edge_h(const float* __restrict__ ea, const float* __restrict__ w,
                         const float* __restrict__ b)
{
    int i = blockIdx.x*blockDim.x + threadIdx.x;
    int e = i >> 6, j = i & 63;
    float acc = b[j];
    #pragma unroll
    for (int k = 0; k < 6; k++) acc += ea[e*6+k]*w[j*6+k];
    g_he[i] = fmaxf(acc, 0.f);
}

__global__ void k_zero(int which)
{
    int i = blockIdx.x*blockDim.x + threadIdx.x;
    if (which == 0) { if (i < N_NODES*D) g_agg[i] = 0.f; }
    else            { if (i < N_NODES)   g_deg[i] = 0.f; }
}

__global__ void k_count(const int* __restrict__ dst)
{
    int e = blockIdx.x*blockDim.x + threadIdx.x;
    if (e < N_EDGES) atomicAdd(&g_deg[dst[e]], 1.f);
}

// 64x64-tile SGEMM, K=64.
// mode 0: g_ew(half) = g_he @ g_e2t + e2_b
// mode 1: g_m = relu(g_out @ root_w + agg/deg + conv_b)
// mode 2: g_gi = g_m @ g_wih_t + gru_bih
// mode 3: g_gh = g_h @ g_whh_t + gru_bhh
__global__ void __launch_bounds__(256)
k_gemm(const float* __restrict__ Bext, const float* __restrict__ bias, int ldb, int mode)
{
    // NOTE: pad must keep rows 16B-aligned (float4 reads) -> pad by 4, align base.
    __shared__ __align__(16) float sAt[64][68];
    __shared__ __align__(16) float sB[64][64];
    const float* A; const float* B;
    if (mode == 0)      { A = g_he;  B = g_e2t; }
    else if (mode == 1) { A = g_out; B = Bext;  }
    else if (mode == 2) { A = g_m;   B = g_wih_t; }
    else                { A = g_h;   B = g_whh_t; }

    int tid = threadIdx.x;
    int e0 = blockIdx.x * 64;
    int j0 = blockIdx.y * 64;
    for (int l = tid; l < 64*64; l += 256) {
        int r = l >> 6, c = l & 63;
        sAt[c][r] = A[(e0 + r)*64 + c];
        sB[r][c]  = B[r*ldb + j0 + c];
    }
    __syncthreads();
    int te = (tid >> 4) << 2;
    int tj = (tid & 15) << 2;
    float acc[4][4] = {};
    #pragma unroll
    for (int k = 0; k < 64; k++) {
        float4 a = *(const float4*)&sAt[k][te];
        float4 b = *(const float4*)&sB[k][tj];
        acc[0][0] += a.x*b.x; acc[0][1] += a.x*b.y; acc[0][2] += a.x*b.z; acc[0][3] += a.x*b.w;
        acc[1][0] += a.y*b.x; acc[1][1] += a.y*b.y; acc[1][2] += a.y*b.z; acc[1][3] += a.y*b.w;
        acc[2][0] += a.z*b.x; acc[2][1] += a.z*b.y; acc[2][2] += a.z*b.z; acc[2][3] += a.z*b.w;
        acc[3][0] += a.w*b.x; acc[3][1] += a.w*b.y; acc[3][2] += a.w*b.z; acc[3][3] += a.w*b.w;
    }
    if (mode == 0) {
        #pragma unroll
        for (int ii = 0; ii < 4; ii++) {
            int row = e0 + te + ii;
            #pragma unroll
            for (int jj = 0; jj < 4; jj++) {
                int col = j0 + tj + jj;
                g_ew[(size_t)row*4096 + col] = __float2half_rn(acc[ii][jj] + bias[col]);
            }
        }
    } else if (mode == 1) {
        #pragma unroll
        for (int ii = 0; ii < 4; ii++) {
            int row = e0 + te + ii;
            float inv = 1.0f/fmaxf(g_deg[row], 1.0f);
            #pragma unroll
            for (int jj = 0; jj < 4; jj++) {
                int col = tj + jj;
                float v = acc[ii][jj] + g_agg[row*64+col]*inv + bias[col];
                g_m[row*64+col] = fmaxf(v, 0.f);
            }
        }
    } else {
        float* C = (mode == 2) ? g_gi : g_gh;
        #pragma unroll
        for (int ii = 0; ii < 4; ii++) {
            int row = e0 + te + ii;
            #pragma unroll
            for (int jj = 0; jj < 4; jj++) {
                int col = j0 + tj + jj;
                C[row*192 + col] = acc[ii][jj] + bias[col];
            }
        }
    }
}

// msg[e] = out[src[e]] @ ew[e]; atomic scatter into agg[dst[e]]
__global__ void __launch_bounds__(256)
k_msg(const int* __restrict__ src, const int* __restrict__ dst)
{
    __shared__ float s_o[8][64];
    int w = threadIdx.x >> 5;
    int lane = threadIdx.x & 31;
    int e = blockIdx.x*8 + w;
    int s = src[e];
    s_o[w][lane]      = g_out[s*64 + lane];
    s_o[w][lane + 32] = g_out[s*64 + 32 + lane];
    __syncwarp();
    const __half2* ewp = (const __half2*)(g_ew + (size_t)e*4096);
    float acc0 = 0.f, acc1 = 0.f;
    #pragma unroll 8
    for (int i = 0; i < 64; i++) {
        float2 f = __half22float2(ewp[i*32 + lane]);
        float a = s_o[w][i];
        acc0 += a*f.x; acc1 += a*f.y;
    }
    int d = dst[e];
    atomicAdd(&g_agg[d*64 + 2*lane],     acc0);
    atomicAdd(&g_agg[d*64 + 2*lane + 1], acc1);
}

__global__ void k_gru()
{
    int i = blockIdx.x*blockDim.x + threadIdx.x;
    int n = i >> 6, j = i & 63;
    const float* gi = g_gi + n*192;
    const float* gh = g_gh + n*192;
    float r  = sigf(gi[j]      + gh[j]);
    float z  = sigf(gi[64+j]   + gh[64+j]);
    float nn = tanhf(gi[128+j] + r*gh[128+j]);
    float h  = g_h[i];
    float hn = (1.f - z)*nn + z*h;
    g_h[i] = hn; g_out[i] = hn;
}

// Set2Set (6 steps) + memory LSTM; one block per graph (contiguous 64-node segments)
__global__ void __launch_bounds__(256)
k_s2s(const float* __restrict__ s2s_bih, const float* __restrict__ s2s_bhh,
      const float* __restrict__ mem_bih, const float* __restrict__ mem_bhh,
      float* __restrict__ d_out, int out_size)
{
    __shared__ float so[64*65];
    __shared__ float sq[128];
    __shared__ float shs[64], scs[64], sg[256], se[64];
    __shared__ float sred[2];
    int g = blockIdx.x, tid = threadIdx.x;
    for (int l = tid; l < 64*64; l += 256) {
        int n = l >> 6, c = l & 63;
        so[n*65+c] = g_out[(g*64+n)*64 + c];
    }
    if (tid < 128) sq[tid] = 0.f;
    if (tid < 64) { shs[tid] = 0.f; scs[tid] = 0.f; }
    __syncthreads();
    for (int step = 0; step < 6; step++) {
        float acc = s2s_bih[tid] + s2s_bhh[tid];
        #pragma unroll 4
        for (int k = 0; k < 128; k++) acc += sq[k]*g_s2s_wih_t[k*256+tid];
        #pragma unroll 4
        for (int k = 0; k < 64;  k++) acc += shs[k]*g_s2s_whh_t[k*256+tid];
        sg[tid] = acc;
        __syncthreads();
        if (tid < 64) {
            float iv = sg[tid], fv = sg[64+tid], gv = sg[128+tid], ov = sg[192+tid];
            float c = sigf(fv)*scs[tid] + sigf(iv)*tanhf(gv);
            scs[tid] = c;
            shs[tid] = sigf(ov)*tanhf(c);
        }
        __syncthreads();
        if (tid < 64) {
            float a = 0.f;
            #pragma unroll 8
            for (int k = 0; k < 64; k++) a += so[tid*65+k]*shs[k];
            se[tid] = a;
        }
        __syncthreads();
        if (tid < 32) {
            float m1 = fmaxf(se[tid], se[tid+32]);
            #pragma unroll
            for (int off = 16; off; off >>= 1) m1 = fmaxf(m1, __shfl_xor_sync(0xffffffffu, m1, off));
            if (tid == 0) sred[0] = m1;
        }
        __syncthreads();
        if (tid < 64) se[tid] = expf(se[tid] - sred[0]);
        __syncthreads();
        if (tid < 32) {
            float s1 = se[tid] + se[tid+32];
            #pragma unroll
            for (int off = 16; off; off >>= 1) s1 += __shfl_xor_sync(0xffffffffu, s1, off);
            if (tid == 0) sred[1] = s1;
        }
        __syncthreads();
        if (tid < 64) {
            float inv = 1.f/sred[1];
            float racc = 0.f;
            #pragma unroll 8
            for (int n = 0; n < 64; n++) racc += se[n]*so[n*65+tid];
            sq[64+tid] = racc*inv;
            sq[tid] = shs[tid];
        }
        __syncthreads();
    }
    float acc = mem_bih[tid] + mem_bhh[tid];
    #pragma unroll 4
    for (int k = 0; k < 128; k++) acc += sq[k]*g_mem_wih_t[k*256+tid];
    sg[tid] = acc;
    __syncthreads();
    if (tid < 64) {
        float iv = sg[tid], gv = sg[128+tid], ov = sg[192+tid];
        float cx = sigf(iv)*tanhf(gv);
        float hx = sigf(ov)*tanhf(cx);
        g_hx[g*64+tid] = hx;
        if (out_size >= NT*6 + 2*NG*D) {
            d_out[NT*6 + g*64 + tid]        = hx;
            d_out[NT*6 + NG*D + g*64 + tid] = cx;
        }
    }
}

// head: feature scramble + lin1(320->64, relu) + lin2(64->6)
__global__ void __launch_bounds__(64)
k_final(const int* __restrict__ nonring, const int* __restrict__ nrbidx,
        const float* __restrict__ lin1_b, const float* __restrict__ lin2_w,
        const float* __restrict__ lin2_b, float* __restrict__ d_out)
{
    __shared__ float sf[320];
    __shared__ float so1[64];
    int r = blockIdx.x, tid = threadIdx.x;
    int ch = r / 48;
    int t  = (r % 48) * 64 + tid;
    sf[tid*5 + 0] = g_hx[nrbidx[t]*64 + ch];
    #pragma unroll
    for (int s = 1; s < 5; s++) {
        int node = nonring[(s-1)*NT + t];
        sf[tid*5 + s] = g_out[node*64 + ch];
    }
    __syncthreads();
    float acc = lin1_b[tid];
    #pragma unroll 8
    for (int q = 0; q < 320; q++) acc += sf[q]*g_lin1_t[q*64+tid];
    so1[tid] = fmaxf(acc, 0.f);
    __syncthreads();
    if (tid < 6) {
        float a2 = lin2_b[tid];
        #pragma unroll 8
        for (int k = 0; k < 64; k++) a2 += so1[k]*lin2_w[tid*64+k];
        d_out[r*6 + tid] = a2;
    }
}

extern "C" void kernel_launch(void* const* d_in, const int* in_sizes, int n_in,
                              void* d_out, int out_size)
{
    const float* x        = (const float*)d_in[0];
    const float* ea       = (const float*)d_in[1];
    const int*   eidx     = (const int*)  d_in[2];
    const int*   nonring  = (const int*)  d_in[4];
    const int*   nrbidx   = (const int*)  d_in[5];
    int base = (n_in >= 32) ? 8 : 6;   // scalar num_graphs/torsion_size present or not
    const float* lin0_w  = (const float*)d_in[base+0];
    const float* lin0_b  = (const float*)d_in[base+1];
    const float* e1_w    = (const float*)d_in[base+2];
    const float* e1_b    = (const float*)d_in[base+3];
    const float* e2_w    = (const float*)d_in[base+4];
    const float* e2_b    = (const float*)d_in[base+5];
    const float* root_w  = (const float*)d_in[base+6];
    const float* conv_b  = (const float*)d_in[base+7];
    const float* gru_wih = (const float*)d_in[base+8];
    const float* gru_whh = (const float*)d_in[base+9];
    const float* gru_bih = (const float*)d_in[base+10];
    const float* gru_bhh = (const float*)d_in[base+11];
    const float* s2s_wih = (const float*)d_in[base+12];
    const float* s2s_whh = (const float*)d_in[base+13];
    const float* s2s_bih = (const float*)d_in[base+14];
    const float* s2s_bhh = (const float*)d_in[base+15];
    const float* mem_wih = (const float*)d_in[base+16];
    const float* mem_bih = (const float*)d_in[base+18];
    const float* mem_bhh = (const float*)d_in[base+19];
    const float* lin1_w  = (const float*)d_in[base+20];
    const float* lin1_b  = (const float*)d_in[base+21];
    const float* lin2_w  = (const float*)d_in[base+22];
    const float* lin2_b  = (const float*)d_in[base+23];
    float* out = (float*)d_out;

    const int* src = eidx;
    const int* dst = eidx + N_EDGES;

    k_prep<<<1024, 256>>>(gru_wih, gru_whh, s2s_wih, s2s_whh, mem_wih, lin1_w, e2_w);
    k_node_init<<<(N_NODES*D)/256, 256>>>(x, lin0_w, lin0_b);
    k_edge_h<<<(N_EDGES*D)/256, 256>>>(ea, e1_w, e1_b);
    k_zero<<<N_NODES/256, 256>>>(1);
    k_count<<<N_EDGES/256, 256>>>(dst);
    k_gemm<<<dim3(N_EDGES/64, 4096/64), 256>>>(nullptr, e2_b, 4096, 0);

    for (int it = 0; it < 6; it++) {
        k_zero<<<(N_NODES*D)/256, 256>>>(0);
        k_msg<<<N_EDGES/8, 256>>>(src, dst);
        k_gemm<<<dim3(N_NODES/64, 1), 256>>>(root_w, conv_b, 64, 1);
        k_gemm<<<dim3(N_NODES/64, 3), 256>>>(nullptr, gru_bih, 192, 2);
        k_gemm<<<dim3(N_NODES/64, 3), 256>>>(nullptr, gru_bhh, 192, 3);
        k_gru<<<(N_NODES*D)/256, 256>>>();
    }

    k_s2s<<<NG, 256>>>(s2s_bih, s2s_bhh, mem_bih, mem_bhh, out, out_size);
    k_final<<<NT, 64>>>(nonring, nrbidx, lin1_b, lin2_w, lin2_b, out);
}